// round 15
// baseline (speedup 1.0000x reference)
#include <cuda_runtime.h>
#include <cstdint>
#include <math.h>

#define B_ 512
#define T_ 8
#define K_ 8192
#define H_ 768
#define F_ 512
#define N1 4096
#define EPSF 1e-8f
#define RMS_EPS 1e-6f

typedef unsigned long long ull;

// ---------------- device scratch ----------------
__device__ float g_x[(size_t)B_ * N1];       // x fp32 pre-norm [m][f]
__device__ float g_xT[(size_t)F_ * N1];      // x_norm transposed [f][m]
__device__ float g_featT[(size_t)H_ * B_];   // features transposed [k][b]
__device__ double g_loss;
__device__ unsigned long long g_count;

// ---------------- helpers ----------------
__device__ __forceinline__ uint32_t smem_u32(const void* p) {
    uint32_t a;
    asm("{ .reg .u64 t; cvta.to.shared.u64 t, %1; cvt.u32.u64 %0, t; }" : "=r"(a) : "l"(p));
    return a;
}
#define CP_ASYNC16(smaddr, gptr) \
    asm volatile("cp.async.cg.shared.global [%0], [%1], 16;" :: "r"(smaddr), "l"(gptr))
#define CP_COMMIT() asm volatile("cp.async.commit_group;" ::: "memory")
#define CP_WAIT0()  asm volatile("cp.async.wait_group 0;" ::: "memory")

__device__ __forceinline__ ull pack_dup(float v) {
    ull d; uint32_t r = __float_as_uint(v);
    asm("mov.b64 %0, {%1, %2};" : "=l"(d) : "r"(r), "r"(r));
    return d;
}
__device__ __forceinline__ void fma2(ull& acc, ull a, ull b) {
    asm("fma.rn.f32x2 %0, %1, %2, %0;" : "+l"(acc) : "l"(a), "l"(b));
}
__device__ __forceinline__ float2 unpack2(ull v) {
    uint32_t lo, hi;
    asm("mov.b64 {%0, %1}, %2;" : "=r"(lo), "=r"(hi) : "l"(v));
    return make_float2(__uint_as_float(lo), __uint_as_float(hi));
}

// ---------------- GEMM1 mainloop (R14 verbatim): 64M x 128N, MP=2 ----------------
#define TS (32 * 132)
#define A1STR 68
#define A1TSZ (32 * A1STR)
__device__ __forceinline__ void mainloop_g1(
    const float* __restrict__ Ak, const float* __restrict__ Bm,
    int rowBase, int colBase, float* sm, ull acc[2][8])
{
    const int tid = threadIdx.x;
    const int tx = tid & 15, ty = tid >> 4;
    float* As[2] = {sm, sm + A1TSZ};
    float* Bs[2] = {sm + 2 * A1TSZ, sm + 2 * A1TSZ + TS};
    const uint32_t asm_[2] = {smem_u32(As[0]), smem_u32(As[1])};
    const uint32_t bsm_[2] = {smem_u32(Bs[0]), smem_u32(Bs[1])};

    auto load_ab = [&](int c, int buf) {
        #pragma unroll
        for (int j = 0; j < 2; j++) {
            int idx = tid + 256 * j;
            int r = idx >> 4, cc = idx & 15;
            CP_ASYNC16(asm_[buf] + (uint32_t)(r * (A1STR * 4) + cc * 16),
                       Ak + (size_t)(c * 32 + r) * B_ + rowBase + cc * 4);
        }
        #pragma unroll
        for (int j = 0; j < 4; j++) {
            int idx = tid + 256 * j;
            int r = idx >> 5, cc = idx & 31;
            CP_ASYNC16(bsm_[buf] + (uint32_t)(r * 528 + cc * 16),
                       Bm + (size_t)(c * 32 + r) * N1 + colBase + cc * 4);
        }
        CP_COMMIT();
    };

    constexpr int NCH = H_ / 32;
    load_ab(0, 0);
    CP_WAIT0();
    __syncthreads();

    for (int c = 0; c < NCH; c++) {
        const int buf = c & 1;
        if (c + 1 < NCH) load_ab(c + 1, buf ^ 1);
        const float* Asb = As[buf];
        const float* Bsb = Bs[buf];
        #pragma unroll
        for (int kk = 0; kk < 32; kk++) {
            ulonglong2 a01 = *reinterpret_cast<const ulonglong2*>(&Asb[kk * A1STR + ty * 4]);
            ull ap[2] = {a01.x, a01.y};
            float4 bv0 = *reinterpret_cast<const float4*>(&Bsb[kk * 132 + tx * 4]);
            float4 bv1 = *reinterpret_cast<const float4*>(&Bsb[kk * 132 + tx * 4 + 64]);
            ull bd[8] = {pack_dup(bv0.x), pack_dup(bv0.y), pack_dup(bv0.z), pack_dup(bv0.w),
                         pack_dup(bv1.x), pack_dup(bv1.y), pack_dup(bv1.z), pack_dup(bv1.w)};
            #pragma unroll
            for (int tp = 0; tp < 2; tp++)
                #pragma unroll
                for (int j = 0; j < 8; j++)
                    fma2(acc[tp][j], ap[tp], bd[j]);
        }
        if (c + 1 < NCH) CP_WAIT0();
        __syncthreads();
    }
}

// ---------------- transpose features (+fused init) ----------------
__global__ void feat_transpose_kernel(const float* __restrict__ in) {
    __shared__ float tile[32][33];
    if (blockIdx.x == 0 && blockIdx.y == 0 && threadIdx.x == 0 && threadIdx.y == 0) {
        g_loss = 0.0; g_count = 0ull;
    }
    int kx = blockIdx.x * 32, by = blockIdx.y * 32;
    int tx = threadIdx.x, ty = threadIdx.y;
    #pragma unroll
    for (int i = ty; i < 32; i += 8) tile[i][tx] = in[(size_t)(by + i) * H_ + kx + tx];
    __syncthreads();
    #pragma unroll
    for (int i = ty; i < 32; i += 8)
        g_featT[(size_t)(kx + i) * B_ + by + tx] = tile[tx][i];
}

// ---------------- GEMM1 (R14 verbatim) ----------------
__global__ __launch_bounds__(256, 2)
void gemm1_kernel(const float* __restrict__ W, const float* __restrict__ bias) {
    extern __shared__ float sm[];
    const int tx = threadIdx.x & 15, ty = threadIdx.x >> 4;
    const int rowBase = blockIdx.y * 64, colBase = blockIdx.x * 128;

    ull acc[2][8];
    #pragma unroll
    for (int tp = 0; tp < 2; tp++)
        #pragma unroll
        for (int j = 0; j < 8; j++) acc[tp][j] = 0ull;

    mainloop_g1(g_featT, W, rowBase, colBase, sm, acc);

    const int c0 = colBase + tx * 4;
    float4 bb0 = *reinterpret_cast<const float4*>(&bias[c0]);
    float4 bb1 = *reinterpret_cast<const float4*>(&bias[c0 + 64]);
    #pragma unroll
    for (int tp = 0; tp < 2; tp++) {
        float2 v[8];
        #pragma unroll
        for (int j = 0; j < 8; j++) v[j] = unpack2(acc[tp][j]);
        int m0 = rowBase + ty * 4 + tp * 2;
        *reinterpret_cast<float4*>(&g_x[(size_t)m0 * N1 + c0]) =
            make_float4(v[0].x + bb0.x, v[1].x + bb0.y, v[2].x + bb0.z, v[3].x + bb0.w);
        *reinterpret_cast<float4*>(&g_x[(size_t)m0 * N1 + c0 + 64]) =
            make_float4(v[4].x + bb1.x, v[5].x + bb1.y, v[6].x + bb1.z, v[7].x + bb1.w);
        *reinterpret_cast<float4*>(&g_x[(size_t)(m0 + 1) * N1 + c0]) =
            make_float4(v[0].y + bb0.x, v[1].y + bb0.y, v[2].y + bb0.z, v[3].y + bb0.w);
        *reinterpret_cast<float4*>(&g_x[(size_t)(m0 + 1) * N1 + c0 + 64]) =
            make_float4(v[4].y + bb1.x, v[5].y + bb1.y, v[6].y + bb1.z, v[7].y + bb1.w);
    }
}

// ---------------- RMS norm (R13/R14 verbatim) ----------------
#define RST 513
__global__ __launch_bounds__(256)
void rms_kernel(const float* __restrict__ norm_w) {
    extern __shared__ float xs[];
    float* scale_s = xs + 32 * RST;
    const int s0 = blockIdx.x * 32;
    const int tid = threadIdx.x;
    const int wid = tid >> 5, lane = tid & 31;

    #pragma unroll
    for (int i = 0; i < 64; i++) {
        int idx = tid + 256 * i;
        int seg = idx >> 9, f = idx & 511;
        xs[seg * RST + f] = g_x[(size_t)(s0 + seg) * F_ + f];
    }
    __syncthreads();

    #pragma unroll
    for (int si = 0; si < 4; si++) {
        int seg = wid * 4 + si;
        float ss = 0.f;
        #pragma unroll
        for (int f = 0; f < 512; f += 32) {
            float v = xs[seg * RST + f + lane];
            ss = fmaf(v, v, ss);
        }
        #pragma unroll
        for (int o = 16; o > 0; o >>= 1) ss += __shfl_xor_sync(0xffffffffu, ss, o);
        if (lane == 0) scale_s[seg] = rsqrtf(ss * (1.0f / F_) + RMS_EPS);
    }
    __syncthreads();

    #pragma unroll
    for (int i = 0; i < 64; i++) {
        int idx = tid + 256 * i;
        int f = idx >> 5, seg = idx & 31;
        g_xT[(size_t)f * N1 + s0 + seg] = xs[seg * RST + f] * scale_s[seg] * norm_w[f];
    }
}

// ---------------- GEMM2 + loss: broadcast-A micro-tile (16 rows x 4 cols) ----------------
// CTA 128M x 128N, 256 thr, 8 warps. Warp w owns rows w*16..+15 (all lanes),
// lane l owns cols l*4..+3. a-loads are warp-broadcast (1 wf), b-load 1x LDS.128
// distinct (4 wf) -> ~8 wf/kk/warp vs ~16 before. Same 32 FFMA2/kk/thread.
#define EV_OFF  (4 * TS)
#define CEN_OFF (EV_OFF + 4096)
#define B2_OFF  (CEN_OFF + 512)
#define SM2_FLOATS (B2_OFF + 128)
__global__ __launch_bounds__(256, 2)
void gemm2_loss_kernel(const float* __restrict__ W2, const float* __restrict__ b2,
                       const unsigned char* __restrict__ is_event,
                       const unsigned char* __restrict__ is_cen,
                       const float* __restrict__ ctr) {
    extern __shared__ float sm[];
    const int tid = threadIdx.x;
    const int lane = tid & 31, wid = tid >> 5;
    const int rowBase = blockIdx.y * 128, colBase = blockIdx.x * 128;
    const int bBase = blockIdx.y * 16;

    const unsigned char* ev_s = reinterpret_cast<const unsigned char*>(sm + EV_OFF);
    const unsigned char* cen_s = reinterpret_cast<const unsigned char*>(sm + CEN_OFF);
    const float* b2_s = sm + B2_OFF;

    // prefetch epilogue operands early
    {
        const uint32_t evb = smem_u32(sm + EV_OFF);
        #pragma unroll
        for (int j = 0; j < 4; j++) {
            int idx = tid + 256 * j;
            int row = idx >> 3, c = idx & 7;
            CP_ASYNC16(evb + (uint32_t)(row * 128 + c * 16),
                       is_event + ((size_t)(bBase * 8 + row)) * K_ + colBase + c * 16);
        }
        if (tid < 128) {
            int row = tid >> 3, c = tid & 7;
            CP_ASYNC16(smem_u32(sm + CEN_OFF) + (uint32_t)(row * 128 + c * 16),
                       is_cen + (size_t)(bBase + row) * K_ + colBase + c * 16);
        }
        if (tid < 32)
            CP_ASYNC16(smem_u32(sm + B2_OFF) + (uint32_t)(tid * 16),
                       b2 + colBase + tid * 4);
        CP_COMMIT();
    }

    float* As[2] = {sm, sm + TS};
    float* Bs[2] = {sm + 2 * TS, sm + 3 * TS};
    const uint32_t asm_[2] = {smem_u32(As[0]), smem_u32(As[1])};
    const uint32_t bsm_[2] = {smem_u32(Bs[0]), smem_u32(Bs[1])};

    auto load_ab = [&](int c, int buf) {
        #pragma unroll
        for (int j = 0; j < 4; j++) {
            int idx = tid + 256 * j;
            int r = idx >> 5, cc = idx & 31;
            CP_ASYNC16(asm_[buf] + (uint32_t)(r * 528 + cc * 16),
                       g_xT + (size_t)(c * 32 + r) * N1 + rowBase + cc * 4);
        }
        #pragma unroll
        for (int j = 0; j < 4; j++) {
            int idx = tid + 256 * j;
            int r = idx >> 5, cc = idx & 31;
            CP_ASYNC16(bsm_[buf] + (uint32_t)(r * 528 + cc * 16),
                       W2 + (size_t)(c * 32 + r) * K_ + colBase + cc * 4);
        }
        CP_COMMIT();
    };

    ull acc[8][4];                 // [row-pair within warp's 16 rows][col j]
    #pragma unroll
    for (int p = 0; p < 8; p++)
        #pragma unroll
        for (int j = 0; j < 4; j++) acc[p][j] = 0ull;

    load_ab(0, 0);
    CP_WAIT0();
    __syncthreads();

    for (int c = 0; c < F_ / 32; c++) {
        const int buf = c & 1;
        if (c + 1 < F_ / 32) load_ab(c + 1, buf ^ 1);
        const float* Asb = As[buf];
        const float* Bsb = Bs[buf];
        #pragma unroll
        for (int kk = 0; kk < 32; kk++) {
            const float* Arow = &Asb[kk * 132 + wid * 16];       // warp-broadcast
            ulonglong2 a0 = *reinterpret_cast<const ulonglong2*>(Arow);
            ulonglong2 a1 = *reinterpret_cast<const ulonglong2*>(Arow + 4);
            ulonglong2 a2 = *reinterpret_cast<const ulonglong2*>(Arow + 8);
            ulonglong2 a3 = *reinterpret_cast<const ulonglong2*>(Arow + 12);
            ull ap[8] = {a0.x, a0.y, a1.x, a1.y, a2.x, a2.y, a3.x, a3.y};
            float4 bv = *reinterpret_cast<const float4*>(&Bsb[kk * 132 + lane * 4]);
            ull bd[4] = {pack_dup(bv.x), pack_dup(bv.y), pack_dup(bv.z), pack_dup(bv.w)};
            #pragma unroll
            for (int p = 0; p < 8; p++)
                #pragma unroll
                for (int j = 0; j < 4; j++)
                    fma2(acc[p][j], ap[p], bd[j]);
        }
        if (c + 1 < F_ / 32) CP_WAIT0();
        __syncthreads();
    }

    // ---- epilogue: thread owns 2 b's (wid*2, wid*2+1) x 4 k-cols ----
    float lloss = 0.f;
    int lcnt = 0;
    #pragma unroll
    for (int g = 0; g < 2; g++) {
        const int b_local = wid * 2 + g;        // 0..15
        const int bglob = bBase + b_local;
        #pragma unroll
        for (int j = 0; j < 4; j++) {
            const int kl = lane * 4 + j;
            const float bb = b2_s[kl];
            float lg[8];
            #pragma unroll
            for (int tp = 0; tp < 4; tp++) {
                float2 p2 = unpack2(acc[g * 4 + tp][j]);
                lg[tp * 2]     = p2.x + bb;
                lg[tp * 2 + 1] = p2.y + bb;
            }
            float mx = lg[0];
            #pragma unroll
            for (int t = 1; t < 8; t++) mx = fmaxf(mx, lg[t]);
            float e[8], s = 0.f;
            #pragma unroll
            for (int t = 0; t < 8; t++) { e[t] = __expf(lg[t] - mx); s += e[t]; }
            const float inv = 1.0f / s;

            const bool cen = cen_s[b_local * 128 + kl] != 0;
            float cdf = 0.f;
            #pragma unroll
            for (int t = 0; t < 8; t++) {
                const float p = e[t] * inv;
                if (ev_s[(b_local * 8 + t) * 128 + kl]) {
                    float integrated = (t == 0) ? 1.0f : (1.0f - cdf);
                    float p_s = fminf(fmaxf(p, EPSF), 1.0f - EPSF);
                    float i_s = fminf(fmaxf(integrated, EPSF), 1.0f - EPSF);
                    float sel;
                    if (cen) {
                        float r = ctr[((size_t)bglob * T_ + t) * K_ + colBase + kl];
                        i_s = fminf(fmaxf(i_s - r * p_s, EPSF), 1.0f - EPSF);
                        sel = i_s;
                    } else {
                        sel = p_s;
                    }
                    lloss += __logf(sel);
                    lcnt++;
                }
                cdf += p;
            }
        }
    }

    #pragma unroll
    for (int o = 16; o > 0; o >>= 1) {
        lloss += __shfl_xor_sync(0xffffffffu, lloss, o);
        lcnt  += __shfl_xor_sync(0xffffffffu, lcnt, o);
    }
    __shared__ float rl[8];
    __shared__ int rc[8];
    if (lane == 0) { rl[wid] = lloss; rc[wid] = lcnt; }
    __syncthreads();
    if (tid == 0) {
        float tl = 0.f; int tc = 0;
        #pragma unroll
        for (int w = 0; w < 8; w++) { tl += rl[w]; tc += rc[w]; }
        atomicAdd(&g_loss, (double)tl);
        atomicAdd(&g_count, (unsigned long long)tc);
    }
}

__global__ void finalize_kernel(float* __restrict__ out) {
    const double H_t = 2.0794415416798357;       // log(8)
    out[0] = (float)(-g_loss / ((double)g_count * H_t));
}

// ---------------- launch ----------------
extern "C" void kernel_launch(void* const* d_in, const int* in_sizes, int n_in,
                              void* d_out, int out_size) {
    const float* features = (const float*)d_in[0];
    const float* W1       = (const float*)d_in[1];
    const float* b1       = (const float*)d_in[2];
    const float* norm_w   = (const float*)d_in[3];
    const float* W2       = (const float*)d_in[4];
    const float* b2       = (const float*)d_in[5];
    const unsigned char* is_event    = (const unsigned char*)d_in[6];
    const unsigned char* is_censored = (const unsigned char*)d_in[7];
    const float* ctr      = (const float*)d_in[8];
    float* out = (float*)d_out;

    const int SMEM1 = (2 * A1TSZ + 2 * TS) * sizeof(float);     // 51200 B
    const int SMEM2 = SM2_FLOATS * sizeof(float);               // 86528 B
    const int SMEMR = (32 * RST + 32) * sizeof(float);          // 65792 B

    static int configured = 0;
    if (!configured) {
        cudaFuncSetAttribute(gemm1_kernel, cudaFuncAttributeMaxDynamicSharedMemorySize, SMEM1);
        cudaFuncSetAttribute(gemm2_loss_kernel, cudaFuncAttributeMaxDynamicSharedMemorySize, SMEM2);
        cudaFuncSetAttribute(rms_kernel, cudaFuncAttributeMaxDynamicSharedMemorySize, SMEMR);
        configured = 1;
    }

    feat_transpose_kernel<<<dim3(H_ / 32, B_ / 32), dim3(32, 8)>>>(features);
    gemm1_kernel<<<dim3(N1 / 128, B_ / 64), 256, SMEM1>>>(W1, b1);
    rms_kernel<<<(B_ * T_) / 32, 256, SMEMR>>>(norm_w);

    gemm2_loss_kernel<<<dim3(K_ / 128, (B_ * T_) / 128), 256, SMEM2>>>(W2, b2, is_event,
                                                                       is_censored, ctr);

    finalize_kernel<<<1, 1>>>(out);
}

// round 16
// speedup vs baseline: 1.1259x; 1.1259x over previous
#include <cuda_runtime.h>
#include <cstdint>
#include <math.h>

#define B_ 512
#define T_ 8
#define K_ 8192
#define H_ 768
#define F_ 512
#define N1 4096
#define EPSF 1e-8f
#define RMS_EPS 1e-6f

typedef unsigned long long ull;

// ---------------- device scratch ----------------
__device__ float g_x[(size_t)B_ * N1];       // x fp32 pre-norm [m][f]
__device__ float g_xT[(size_t)F_ * N1];      // x_norm transposed [f][m]
__device__ float g_featT[(size_t)H_ * B_];   // features transposed [k][b]
__device__ double g_loss;
__device__ unsigned long long g_count;

// ---------------- helpers ----------------
__device__ __forceinline__ uint32_t smem_u32(const void* p) {
    uint32_t a;
    asm("{ .reg .u64 t; cvta.to.shared.u64 t, %1; cvt.u32.u64 %0, t; }" : "=r"(a) : "l"(p));
    return a;
}
#define CP_ASYNC16(smaddr, gptr) \
    asm volatile("cp.async.cg.shared.global [%0], [%1], 16;" :: "r"(smaddr), "l"(gptr))
#define CP_COMMIT() asm volatile("cp.async.commit_group;" ::: "memory")
#define CP_WAIT0()  asm volatile("cp.async.wait_group 0;" ::: "memory")

__device__ __forceinline__ ull pack_dup(float v) {
    ull d; uint32_t r = __float_as_uint(v);
    asm("mov.b64 %0, {%1, %2};" : "=l"(d) : "r"(r), "r"(r));
    return d;
}
__device__ __forceinline__ void fma2(ull& acc, ull a, ull b) {
    asm("fma.rn.f32x2 %0, %1, %2, %0;" : "+l"(acc) : "l"(a), "l"(b));
}
__device__ __forceinline__ float2 unpack2(ull v) {
    uint32_t lo, hi;
    asm("mov.b64 {%0, %1}, %2;" : "=r"(lo), "=r"(hi) : "l"(v));
    return make_float2(__uint_as_float(lo), __uint_as_float(hi));
}

// ---------------- GEMM1 mainloop (R14 verbatim): 64M x 128N, MP=2 ----------------
#define TS (32 * 132)
#define A1STR 68
#define A1TSZ (32 * A1STR)
__device__ __forceinline__ void mainloop_g1(
    const float* __restrict__ Ak, const float* __restrict__ Bm,
    int rowBase, int colBase, float* sm, ull acc[2][8])
{
    const int tid = threadIdx.x;
    const int tx = tid & 15, ty = tid >> 4;
    float* As[2] = {sm, sm + A1TSZ};
    float* Bs[2] = {sm + 2 * A1TSZ, sm + 2 * A1TSZ + TS};
    const uint32_t asm_[2] = {smem_u32(As[0]), smem_u32(As[1])};
    const uint32_t bsm_[2] = {smem_u32(Bs[0]), smem_u32(Bs[1])};

    auto load_ab = [&](int c, int buf) {
        #pragma unroll
        for (int j = 0; j < 2; j++) {
            int idx = tid + 256 * j;
            int r = idx >> 4, cc = idx & 15;
            CP_ASYNC16(asm_[buf] + (uint32_t)(r * (A1STR * 4) + cc * 16),
                       Ak + (size_t)(c * 32 + r) * B_ + rowBase + cc * 4);
        }
        #pragma unroll
        for (int j = 0; j < 4; j++) {
            int idx = tid + 256 * j;
            int r = idx >> 5, cc = idx & 31;
            CP_ASYNC16(bsm_[buf] + (uint32_t)(r * 528 + cc * 16),
                       Bm + (size_t)(c * 32 + r) * N1 + colBase + cc * 4);
        }
        CP_COMMIT();
    };

    constexpr int NCH = H_ / 32;
    load_ab(0, 0);
    CP_WAIT0();
    __syncthreads();

    for (int c = 0; c < NCH; c++) {
        const int buf = c & 1;
        if (c + 1 < NCH) load_ab(c + 1, buf ^ 1);
        const float* Asb = As[buf];
        const float* Bsb = Bs[buf];
        #pragma unroll
        for (int kk = 0; kk < 32; kk++) {
            ulonglong2 a01 = *reinterpret_cast<const ulonglong2*>(&Asb[kk * A1STR + ty * 4]);
            ull ap[2] = {a01.x, a01.y};
            float4 bv0 = *reinterpret_cast<const float4*>(&Bsb[kk * 132 + tx * 4]);
            float4 bv1 = *reinterpret_cast<const float4*>(&Bsb[kk * 132 + tx * 4 + 64]);
            ull bd[8] = {pack_dup(bv0.x), pack_dup(bv0.y), pack_dup(bv0.z), pack_dup(bv0.w),
                         pack_dup(bv1.x), pack_dup(bv1.y), pack_dup(bv1.z), pack_dup(bv1.w)};
            #pragma unroll
            for (int tp = 0; tp < 2; tp++)
                #pragma unroll
                for (int j = 0; j < 8; j++)
                    fma2(acc[tp][j], ap[tp], bd[j]);
        }
        if (c + 1 < NCH) CP_WAIT0();
        __syncthreads();
    }
}

// ---------------- transpose features (+fused init) ----------------
__global__ void feat_transpose_kernel(const float* __restrict__ in) {
    __shared__ float tile[32][33];
    if (blockIdx.x == 0 && blockIdx.y == 0 && threadIdx.x == 0 && threadIdx.y == 0) {
        g_loss = 0.0; g_count = 0ull;
    }
    int kx = blockIdx.x * 32, by = blockIdx.y * 32;
    int tx = threadIdx.x, ty = threadIdx.y;
    #pragma unroll
    for (int i = ty; i < 32; i += 8) tile[i][tx] = in[(size_t)(by + i) * H_ + kx + tx];
    __syncthreads();
    #pragma unroll
    for (int i = ty; i < 32; i += 8)
        g_featT[(size_t)(kx + i) * B_ + by + tx] = tile[tx][i];
}

// ---------------- GEMM1 (R14 verbatim) ----------------
__global__ __launch_bounds__(256, 2)
void gemm1_kernel(const float* __restrict__ W, const float* __restrict__ bias) {
    extern __shared__ float sm[];
    const int tx = threadIdx.x & 15, ty = threadIdx.x >> 4;
    const int rowBase = blockIdx.y * 64, colBase = blockIdx.x * 128;

    ull acc[2][8];
    #pragma unroll
    for (int tp = 0; tp < 2; tp++)
        #pragma unroll
        for (int j = 0; j < 8; j++) acc[tp][j] = 0ull;

    mainloop_g1(g_featT, W, rowBase, colBase, sm, acc);

    const int c0 = colBase + tx * 4;
    float4 bb0 = *reinterpret_cast<const float4*>(&bias[c0]);
    float4 bb1 = *reinterpret_cast<const float4*>(&bias[c0 + 64]);
    #pragma unroll
    for (int tp = 0; tp < 2; tp++) {
        float2 v[8];
        #pragma unroll
        for (int j = 0; j < 8; j++) v[j] = unpack2(acc[tp][j]);
        int m0 = rowBase + ty * 4 + tp * 2;
        *reinterpret_cast<float4*>(&g_x[(size_t)m0 * N1 + c0]) =
            make_float4(v[0].x + bb0.x, v[1].x + bb0.y, v[2].x + bb0.z, v[3].x + bb0.w);
        *reinterpret_cast<float4*>(&g_x[(size_t)m0 * N1 + c0 + 64]) =
            make_float4(v[4].x + bb1.x, v[5].x + bb1.y, v[6].x + bb1.z, v[7].x + bb1.w);
        *reinterpret_cast<float4*>(&g_x[(size_t)(m0 + 1) * N1 + c0]) =
            make_float4(v[0].y + bb0.x, v[1].y + bb0.y, v[2].y + bb0.z, v[3].y + bb0.w);
        *reinterpret_cast<float4*>(&g_x[(size_t)(m0 + 1) * N1 + c0 + 64]) =
            make_float4(v[4].y + bb1.x, v[5].y + bb1.y, v[6].y + bb1.z, v[7].y + bb1.w);
    }
}

// ---------------- RMS norm: 16 segments/block, 256 blocks (better occupancy) ----------------
#define RST 513
#define RSEG 16
__global__ __launch_bounds__(256)
void rms_kernel(const float* __restrict__ norm_w) {
    extern __shared__ float xs[];
    float* scale_s = xs + RSEG * RST;
    const int s0 = blockIdx.x * RSEG;
    const int tid = threadIdx.x;
    const int wid = tid >> 5, lane = tid & 31;

    #pragma unroll
    for (int i = 0; i < 32; i++) {               // 16 segs x 512 f coalesced
        int idx = tid + 256 * i;
        int seg = idx >> 9, f = idx & 511;
        xs[seg * RST + f] = g_x[(size_t)(s0 + seg) * F_ + f];
    }
    __syncthreads();

    #pragma unroll
    for (int si = 0; si < 2; si++) {             // 8 warps x 2 segs
        int seg = wid * 2 + si;
        float ss = 0.f;
        #pragma unroll
        for (int f = 0; f < 512; f += 32) {
            float v = xs[seg * RST + f + lane];
            ss = fmaf(v, v, ss);
        }
        #pragma unroll
        for (int o = 16; o > 0; o >>= 1) ss += __shfl_xor_sync(0xffffffffu, ss, o);
        if (lane == 0) scale_s[seg] = rsqrtf(ss * (1.0f / F_) + RMS_EPS);
    }
    __syncthreads();

    #pragma unroll
    for (int i = 0; i < 32; i++) {               // coalesced transposed write
        int idx = tid + 256 * i;
        int f = idx >> 4, seg = idx & 15;
        g_xT[(size_t)f * N1 + s0 + seg] = xs[seg * RST + f] * scale_s[seg] * norm_w[f];
    }
}

// ---------------- GEMM2 + loss (R14 mainloop verbatim; hoisted ctr gathers) ----------------
#define EV_OFF  (4 * TS)
#define CEN_OFF (EV_OFF + 4096)
#define B2_OFF  (CEN_OFF + 512)
#define SM2_FLOATS (B2_OFF + 128)
__global__ __launch_bounds__(256, 2)
void gemm2_loss_kernel(const float* __restrict__ W2, const float* __restrict__ b2,
                       const unsigned char* __restrict__ is_event,
                       const unsigned char* __restrict__ is_cen,
                       const float* __restrict__ ctr) {
    extern __shared__ float sm[];
    const int tid = threadIdx.x;
    const int tx = tid & 15, ty = tid >> 4;
    const int rowBase = blockIdx.y * 128, colBase = blockIdx.x * 128;
    const int bBase = blockIdx.y * 16;
    const int bglob = bBase + ty;

    const unsigned char* ev_s = reinterpret_cast<const unsigned char*>(sm + EV_OFF);
    const unsigned char* cen_s = reinterpret_cast<const unsigned char*>(sm + CEN_OFF);
    const float* b2_s = sm + B2_OFF;

    // prefetch epilogue operands early
    {
        const uint32_t evb = smem_u32(sm + EV_OFF);
        #pragma unroll
        for (int j = 0; j < 4; j++) {
            int idx = tid + 256 * j;
            int row = idx >> 3, c = idx & 7;
            CP_ASYNC16(evb + (uint32_t)(row * 128 + c * 16),
                       is_event + ((size_t)(bBase * 8 + row)) * K_ + colBase + c * 16);
        }
        if (tid < 128) {
            int row = tid >> 3, c = tid & 7;
            CP_ASYNC16(smem_u32(sm + CEN_OFF) + (uint32_t)(row * 128 + c * 16),
                       is_cen + (size_t)(bBase + row) * K_ + colBase + c * 16);
        }
        if (tid < 32)
            CP_ASYNC16(smem_u32(sm + B2_OFF) + (uint32_t)(tid * 16),
                       b2 + colBase + tid * 4);
        CP_COMMIT();
    }

    float* As[2] = {sm, sm + TS};
    float* Bs[2] = {sm + 2 * TS, sm + 3 * TS};
    const uint32_t asm_[2] = {smem_u32(As[0]), smem_u32(As[1])};
    const uint32_t bsm_[2] = {smem_u32(Bs[0]), smem_u32(Bs[1])};

    auto load_ab = [&](int c, int buf) {
        #pragma unroll
        for (int j = 0; j < 4; j++) {
            int idx = tid + 256 * j;
            int r = idx >> 5, cc = idx & 31;
            CP_ASYNC16(asm_[buf] + (uint32_t)(r * 528 + cc * 16),
                       g_xT + (size_t)(c * 32 + r) * N1 + rowBase + cc * 4);
        }
        #pragma unroll
        for (int j = 0; j < 4; j++) {
            int idx = tid + 256 * j;
            int r = idx >> 5, cc = idx & 31;
            CP_ASYNC16(bsm_[buf] + (uint32_t)(r * 528 + cc * 16),
                       W2 + (size_t)(c * 32 + r) * K_ + colBase + cc * 4);
        }
        CP_COMMIT();
    };

    ull acc[4][8];
    #pragma unroll
    for (int tp = 0; tp < 4; tp++)
        #pragma unroll
        for (int j = 0; j < 8; j++) acc[tp][j] = 0ull;

    load_ab(0, 0);
    CP_WAIT0();
    __syncthreads();

    for (int c = 0; c < F_ / 32; c++) {
        const int buf = c & 1;
        if (c + 1 < F_ / 32) load_ab(c + 1, buf ^ 1);
        const float* Asb = As[buf];
        const float* Bsb = Bs[buf];
        #pragma unroll
        for (int kk = 0; kk < 32; kk++) {
            ulonglong2 a01 = *reinterpret_cast<const ulonglong2*>(&Asb[kk * 132 + ty * 8]);
            ulonglong2 a23 = *reinterpret_cast<const ulonglong2*>(&Asb[kk * 132 + ty * 8 + 4]);
            ull ap[4] = {a01.x, a01.y, a23.x, a23.y};
            float4 bv0 = *reinterpret_cast<const float4*>(&Bsb[kk * 132 + tx * 4]);
            float4 bv1 = *reinterpret_cast<const float4*>(&Bsb[kk * 132 + tx * 4 + 64]);
            ull bd[8] = {pack_dup(bv0.x), pack_dup(bv0.y), pack_dup(bv0.z), pack_dup(bv0.w),
                         pack_dup(bv1.x), pack_dup(bv1.y), pack_dup(bv1.z), pack_dup(bv1.w)};
            #pragma unroll
            for (int tp = 0; tp < 4; tp++)
                #pragma unroll
                for (int j = 0; j < 8; j++)
                    fma2(acc[tp][j], ap[tp], bd[j]);
        }
        if (c + 1 < F_ / 32) CP_WAIT0();
        __syncthreads();
    }

    // ---- epilogue phase 1: find event-t per (b,k) column, issue all ctr gathers ----
    int tev[8];
    float rv[8];
    #pragma unroll
    for (int j = 0; j < 8; j++) {
        const int kl = tx * 4 + (j & 3) + ((j >= 4) ? 64 : 0);
        int te = 0;
        #pragma unroll
        for (int t = 1; t < 8; t++)
            if (ev_s[(ty * 8 + t) * 128 + kl]) te = t;
        tev[j] = te;
        rv[j] = ctr[((size_t)bglob * T_ + te) * K_ + colBase + kl];  // MLP=8 gathers
    }

    // ---- epilogue phase 2: softmax + loss (math identical to R14) ----
    float lloss = 0.f;
    int lcnt = 0;
    #pragma unroll
    for (int j = 0; j < 8; j++) {
        const int kl = tx * 4 + (j & 3) + ((j >= 4) ? 64 : 0);
        const float bb = b2_s[kl];
        float lg[8];
        #pragma unroll
        for (int tp = 0; tp < 4; tp++) {
            float2 p2 = unpack2(acc[tp][j]);
            lg[tp * 2]     = p2.x + bb;
            lg[tp * 2 + 1] = p2.y + bb;
        }
        float mx = lg[0];
        #pragma unroll
        for (int t = 1; t < 8; t++) mx = fmaxf(mx, lg[t]);
        float e[8], s = 0.f;
        #pragma unroll
        for (int t = 0; t < 8; t++) { e[t] = __expf(lg[t] - mx); s += e[t]; }
        const float inv = 1.0f / s;

        const bool cen = cen_s[ty * 128 + kl] != 0;
        float cdf = 0.f;
        #pragma unroll
        for (int t = 0; t < 8; t++) {
            const float p = e[t] * inv;
            if (ev_s[(ty * 8 + t) * 128 + kl]) {
                float integrated = (t == 0) ? 1.0f : (1.0f - cdf);
                float p_s = fminf(fmaxf(p, EPSF), 1.0f - EPSF);
                float i_s = fminf(fmaxf(integrated, EPSF), 1.0f - EPSF);
                float sel;
                if (cen) {
                    i_s = fminf(fmaxf(i_s - rv[j] * p_s, EPSF), 1.0f - EPSF);
                    sel = i_s;
                } else {
                    sel = p_s;
                }
                lloss += __logf(sel);
                lcnt++;
            }
            cdf += p;
        }
    }

    #pragma unroll
    for (int o = 16; o > 0; o >>= 1) {
        lloss += __shfl_xor_sync(0xffffffffu, lloss, o);
        lcnt  += __shfl_xor_sync(0xffffffffu, lcnt, o);
    }
    __shared__ float rl[8];
    __shared__ int rc[8];
    if ((tid & 31) == 0) { rl[tid >> 5] = lloss; rc[tid >> 5] = lcnt; }
    __syncthreads();
    if (tid == 0) {
        float tl = 0.f; int tc = 0;
        #pragma unroll
        for (int w = 0; w < 8; w++) { tl += rl[w]; tc += rc[w]; }
        atomicAdd(&g_loss, (double)tl);
        atomicAdd(&g_count, (unsigned long long)tc);
    }
}

__global__ void finalize_kernel(float* __restrict__ out) {
    const double H_t = 2.0794415416798357;       // log(8)
    out[0] = (float)(-g_loss / ((double)g_count * H_t));
}

// ---------------- launch ----------------
extern "C" void kernel_launch(void* const* d_in, const int* in_sizes, int n_in,
                              void* d_out, int out_size) {
    const float* features = (const float*)d_in[0];
    const float* W1       = (const float*)d_in[1];
    const float* b1       = (const float*)d_in[2];
    const float* norm_w   = (const float*)d_in[3];
    const float* W2       = (const float*)d_in[4];
    const float* b2       = (const float*)d_in[5];
    const unsigned char* is_event    = (const unsigned char*)d_in[6];
    const unsigned char* is_censored = (const unsigned char*)d_in[7];
    const float* ctr      = (const float*)d_in[8];
    float* out = (float*)d_out;

    const int SMEM1 = (2 * A1TSZ + 2 * TS) * sizeof(float);     // 51200 B
    const int SMEM2 = SM2_FLOATS * sizeof(float);               // 86528 B
    const int SMEMR = (RSEG * RST + RSEG) * sizeof(float);      // 32896 B

    static int configured = 0;
    if (!configured) {
        cudaFuncSetAttribute(gemm1_kernel, cudaFuncAttributeMaxDynamicSharedMemorySize, SMEM1);
        cudaFuncSetAttribute(gemm2_loss_kernel, cudaFuncAttributeMaxDynamicSharedMemorySize, SMEM2);
        cudaFuncSetAttribute(rms_kernel, cudaFuncAttributeMaxDynamicSharedMemorySize, SMEMR);
        configured = 1;
    }

    feat_transpose_kernel<<<dim3(H_ / 32, B_ / 32), dim3(32, 8)>>>(features);
    gemm1_kernel<<<dim3(N1 / 128, B_ / 64), 256, SMEM1>>>(W1, b1);
    rms_kernel<<<(B_ * T_) / RSEG, 256, SMEMR>>>(norm_w);

    gemm2_loss_kernel<<<dim3(K_ / 128, (B_ * T_) / 128), 256, SMEM2>>>(W2, b2, is_event,
                                                                       is_censored, ctr);

    finalize_kernel<<<1, 1>>>(out);
}